// round 11
// baseline (speedup 1.0000x reference)
#include <cuda_runtime.h>
#include <cuda_fp16.h>

#define N_CAP 100000
#define E_CAP 1600000
#define F_DIM 128

// -------- static scratch (allocation-free rule) --------
__device__ uint2 g_xh [(size_t)N_CAP * 32];   // x  rows in fp16 (25.6 MB)
__device__ uint2 g_h1h[(size_t)N_CAP * 32];   // h1 rows in fp16 (25.6 MB)
__device__ float g_dinv[N_CAP];
__device__ int   g_rowptr[N_CAP + 1];
__device__ int   g_cnt[N_CAP];                // zero-init; hist adds; scan reads + re-zeros
__device__ int   g_cur[N_CAP];                // scatter cursor
__device__ int2  g_cw[E_CAP];                 // (src, bitcast(dinv[src])) sorted by dst
__device__ int   g_is64;

// -------- 1) fused: dtype detect (per-block) + x->fp16 + dst histogram --------
__global__ void histcvt_k(const float2* __restrict__ x, const void* ei,
                          int NF2, int E) {
    __shared__ int s_is64;
    if (threadIdx.x < 32) {
        const long long* el = (const long long*)ei;
        int ok = 1;
        #pragma unroll
        for (int i = threadIdx.x; i < 128; i += 32) {
            long long v = el[i];
            if (v < 0 || v >= (1LL << 31)) ok = 0;
        }
        ok = __all_sync(0xffffffffu, ok);
        if (threadIdx.x == 0) { s_is64 = ok; if (blockIdx.x == 0) g_is64 = ok; }
    }
    __syncthreads();
    int is64   = s_is64;
    int idx    = blockIdx.x * blockDim.x + threadIdx.x;
    int stride = gridDim.x * blockDim.x;
    for (int i = idx; i < NF2; i += stride) {
        float2 v = x[i];
        ((__half2*)g_xh)[i] = __floats2half2_rn(v.x, v.y);
    }
    for (int e = idx; e < E; e += stride) {
        int dst = is64 ? (int)((const long long*)ei)[(size_t)E + e]
                       : ((const int*)ei)[(size_t)E + e];
        atomicAdd(&g_cnt[dst], 1);
    }
}

// -------- 2) single-block scan: rowptr + cursor + dinv, re-zero g_cnt --------
__global__ void __launch_bounds__(1024) scan_k(int N) {
    __shared__ int warp_off[32];
    __shared__ int s_carry;
    int tid  = threadIdx.x;
    int lane = tid & 31, wid = tid >> 5;
    if (tid == 0) s_carry = 0;
    __syncthreads();
    for (int base = 0; base < N; base += 1024) {
        int i = base + tid;
        int v = (i < N) ? g_cnt[i] : 0;
        int incl = v;
        #pragma unroll
        for (int o = 1; o < 32; o <<= 1) {
            int t = __shfl_up_sync(0xffffffffu, incl, o);
            if (lane >= o) incl += t;
        }
        if (lane == 31) warp_off[wid] = incl;
        __syncthreads();
        if (wid == 0) {
            int ws = warp_off[lane];
            int wincl = ws;
            #pragma unroll
            for (int o = 1; o < 32; o <<= 1) {
                int t = __shfl_up_sync(0xffffffffu, wincl, o);
                if (lane >= o) wincl += t;
            }
            warp_off[lane] = wincl - ws;      // exclusive per-warp offset
        }
        __syncthreads();
        int excl = s_carry + warp_off[wid] + incl - v;
        if (i < N) {
            g_rowptr[i] = excl;
            g_cur[i]    = excl;
            g_dinv[i]   = rsqrtf((float)v + 1.0f);
            g_cnt[i]    = 0;                  // ready for next call's histogram
        }
        __syncthreads();
        if (tid == 1023) s_carry = excl + v;  // carry + tile total
        __syncthreads();
    }
    if (tid == 0) g_rowptr[N] = s_carry;
}

// -------- 3) scatter edges into CSR with precomputed source weight --------
__global__ void scatter_k(const void* ei, int E) {
    int e = blockIdx.x * blockDim.x + threadIdx.x;
    if (e >= E) return;
    int src, dst;
    if (g_is64) {
        src = (int)((const long long*)ei)[e];
        dst = (int)((const long long*)ei)[(size_t)E + e];
    } else {
        src = ((const int*)ei)[e];
        dst = ((const int*)ei)[(size_t)E + e];
    }
    int pos = atomicAdd(&g_cur[dst], 1);
    g_cw[pos] = make_int2(src, __float_as_int(g_dinv[src]));
}

// -------- gather core: warp-uniform edge loads, fp16 rows, fp32 acc --------
__device__ __forceinline__ float4 hop_row(const uint2* __restrict__ tab,
                                          int gw, int lane) {
    int beg = g_rowptr[gw], end = g_rowptr[gw + 1];
    float4 acc = make_float4(0.f, 0.f, 0.f, 0.f);
    int j = beg;
    for (; j + 3 < end; j += 4) {
        int2 c0 = __ldcs(&g_cw[j]);
        int2 c1 = __ldcs(&g_cw[j + 1]);
        int2 c2 = __ldcs(&g_cw[j + 2]);
        int2 c3 = __ldcs(&g_cw[j + 3]);
        uint2 u0 = tab[(size_t)c0.x * 32 + lane];
        uint2 u1 = tab[(size_t)c1.x * 32 + lane];
        uint2 u2 = tab[(size_t)c2.x * 32 + lane];
        uint2 u3 = tab[(size_t)c3.x * 32 + lane];
        float w0 = __int_as_float(c0.y), w1 = __int_as_float(c1.y);
        float w2 = __int_as_float(c2.y), w3 = __int_as_float(c3.y);
        float2 a0 = __half22float2(*(const __half2*)&u0.x);
        float2 b0 = __half22float2(*(const __half2*)&u0.y);
        float2 a1 = __half22float2(*(const __half2*)&u1.x);
        float2 b1 = __half22float2(*(const __half2*)&u1.y);
        float2 a2 = __half22float2(*(const __half2*)&u2.x);
        float2 b2 = __half22float2(*(const __half2*)&u2.y);
        float2 a3 = __half22float2(*(const __half2*)&u3.x);
        float2 b3 = __half22float2(*(const __half2*)&u3.y);
        acc.x = fmaf(w0, a0.x, fmaf(w1, a1.x, fmaf(w2, a2.x, fmaf(w3, a3.x, acc.x))));
        acc.y = fmaf(w0, a0.y, fmaf(w1, a1.y, fmaf(w2, a2.y, fmaf(w3, a3.y, acc.y))));
        acc.z = fmaf(w0, b0.x, fmaf(w1, b1.x, fmaf(w2, b2.x, fmaf(w3, b3.x, acc.z))));
        acc.w = fmaf(w0, b0.y, fmaf(w1, b1.y, fmaf(w2, b2.y, fmaf(w3, b3.y, acc.w))));
    }
    for (; j < end; j++) {
        int2  c = __ldcs(&g_cw[j]);
        float w = __int_as_float(c.y);
        uint2 u = tab[(size_t)c.x * 32 + lane];
        float2 a = __half22float2(*(const __half2*)&u.x);
        float2 b = __half22float2(*(const __half2*)&u.y);
        acc.x = fmaf(w, a.x, acc.x);
        acc.y = fmaf(w, a.y, acc.y);
        acc.z = fmaf(w, b.x, acc.z);
        acc.w = fmaf(w, b.y, acc.w);
    }
    float  di = g_dinv[gw];
    uint2  u  = tab[(size_t)gw * 32 + lane];
    float2 a  = __half22float2(*(const __half2*)&u.x);
    float2 b  = __half22float2(*(const __half2*)&u.y);
    float  sl = di * di;
    acc.x = di * acc.x + sl * a.x;
    acc.y = di * acc.y + sl * a.y;
    acc.z = di * acc.z + sl * b.x;
    acc.w = di * acc.w + sl * b.y;
    return acc;
}

// -------- 4) hop 1 (captured by ncu) --------
__global__ void __launch_bounds__(256) hop1_k(int N) {
    int gw   = (blockIdx.x * blockDim.x + threadIdx.x) >> 5;
    int lane = threadIdx.x & 31;
    if (gw >= N) return;
    float4 acc = hop_row(g_xh, gw, lane);
    uint2 o;
    *(__half2*)&o.x = __floats2half2_rn(acc.x, acc.y);
    *(__half2*)&o.y = __floats2half2_rn(acc.z, acc.w);
    g_h1h[(size_t)gw * 32 + lane] = o;
}

// -------- 5) hop 2 fused with linear projection --------
__global__ void __launch_bounds__(256) hop2_gemm_k(const float* __restrict__ W,
                                                   const float* __restrict__ b,
                                                   float* __restrict__ out,
                                                   int N, int C) {
    extern __shared__ float sm[];               // C*F + C floats
    const float4* sW4 = (const float4*)sm;
    float*        sb  = sm + C * F_DIM;
    for (int idx = threadIdx.x; idx < C * F_DIM; idx += blockDim.x) sm[idx] = W[idx];
    for (int idx = threadIdx.x; idx < C; idx += blockDim.x) sb[idx] = b[idx];
    __syncthreads();

    int gw   = (blockIdx.x * blockDim.x + threadIdx.x) >> 5;
    int lane = threadIdx.x & 31;
    if (gw >= N) return;

    float4 acc = hop_row(g_h1h, gw, lane);

    float my0 = 0.f, my1 = 0.f;
    for (int c = 0; c < C; c++) {
        float4 wv = sW4[c * 32 + lane];
        float p = acc.x * wv.x + acc.y * wv.y + acc.z * wv.z + acc.w * wv.w;
        p += __shfl_xor_sync(0xffffffffu, p, 16);
        p += __shfl_xor_sync(0xffffffffu, p, 8);
        p += __shfl_xor_sync(0xffffffffu, p, 4);
        p += __shfl_xor_sync(0xffffffffu, p, 2);
        p += __shfl_xor_sync(0xffffffffu, p, 1);
        p += sb[c];
        if (c < 32) { if (lane == c)      my0 = p; }
        else        { if (lane == c - 32) my1 = p; }
    }
    float* orow = out + (size_t)gw * C;
    __stcs(&orow[lane], my0);
    if (lane < C - 32) __stcs(&orow[32 + lane], my1);
}

extern "C" void kernel_launch(void* const* d_in, const int* in_sizes, int n_in,
                              void* d_out, int out_size) {
    const float* x  = (const float*)d_in[0];
    const void*  ei = d_in[1];
    const float* W  = (const float*)d_in[2];
    const float* b  = (const float*)d_in[3];

    int C   = in_sizes[3];                 // 40
    int F   = in_sizes[2] / C;             // 128
    int N   = in_sizes[0] / F;             // 100000
    int E   = in_sizes[1] / 2;             // 1600000
    int NF2 = N * F / 2;

    histcvt_k<<<1184, 256>>>((const float2*)x, ei, NF2, E);   // 1
    scan_k<<<1, 1024>>>(N);                                   // 2
    scatter_k<<<(E + 255) / 256, 256>>>(ei, E);               // 3
    int blocks = (N * 32 + 255) / 256;     // warp per node
    hop1_k<<<blocks, 256>>>(N);                               // 4  <- ncu capture
    size_t shmem = (size_t)(C * F_DIM + C) * sizeof(float);
    hop2_gemm_k<<<blocks, 256, shmem>>>(W, b, (float*)d_out, N, C);  // 5
}

// round 12
// speedup vs baseline: 1.7886x; 1.7886x over previous
#include <cuda_runtime.h>

#define N_CAP 100000
#define E_CAP 1600000
#define F_DIM 128

// -------- static scratch (allocation-free rule) --------
__device__ float g_h1[(size_t)N_CAP * F_DIM];  // hop-1 result fp32 (51.2 MB)
__device__ float g_dinv[N_CAP];
__device__ int   g_rowptr[N_CAP + 1];
__device__ int   g_cnt[N_CAP];                 // histogram -> cursor
__device__ int2  g_cw[E_CAP];                  // (src*32, bitcast(dinv[src])) by dst
__device__ int   g_bsums[1024];
__device__ int   g_is64;

// -------- 1) prep: zero histogram + parallel dtype detect --------
__global__ void prep_k(const void* ei, int N) {
    if (blockIdx.x == 0 && threadIdx.x < 32) {
        const long long* el = (const long long*)ei;
        int ok = 1;
        #pragma unroll
        for (int i = threadIdx.x; i < 128; i += 32) {
            long long v = el[i];
            if (v < 0 || v >= (1LL << 31)) ok = 0;
        }
        ok = __all_sync(0xffffffffu, ok);
        if (threadIdx.x == 0) g_is64 = ok;
    }
    int idx = blockIdx.x * blockDim.x + threadIdx.x;
    if (idx < N) g_cnt[idx] = 0;
}

// -------- 2) histogram of dst --------
__global__ void hist_k(const void* ei, int E) {
    int e = blockIdx.x * blockDim.x + threadIdx.x;
    if (e >= E) return;
    int dst;
    if (g_is64) dst = (int)((const long long*)ei)[(size_t)E + e];
    else        dst = ((const int*)ei)[(size_t)E + e];
    atomicAdd(&g_cnt[dst], 1);
}

// -------- 3) per-1024-chunk totals --------
__global__ void scan1_k(int N) {
    __shared__ int sh[256];
    int base = blockIdx.x * 1024;
    int tid  = threadIdx.x;
    int s = 0;
    #pragma unroll
    for (int k = 0; k < 4; k++) {
        int i = base + tid + k * 256;
        if (i < N) s += g_cnt[i];
    }
    sh[tid] = s; __syncthreads();
    for (int off = 128; off > 0; off >>= 1) {
        if (tid < off) sh[tid] += sh[tid + off];
        __syncthreads();
    }
    if (tid == 0) g_bsums[blockIdx.x] = sh[0];
}

// -------- 4) fused: block prefix + local scan + rowptr + cursor + dinv --------
__global__ void scan3_k(int N) {
    __shared__ int sh[1024];
    __shared__ int bpref;
    int tid = threadIdx.x, bid = blockIdx.x;
    if (tid < 32) {
        int s = 0;
        for (int b = tid; b < bid; b += 32) s += g_bsums[b];
        #pragma unroll
        for (int o = 16; o > 0; o >>= 1) s += __shfl_xor_sync(0xffffffffu, s, o);
        if (tid == 0) bpref = s;
    }
    int i   = bid * 1024 + tid;
    int own = (i < N) ? g_cnt[i] : 0;
    sh[tid] = own; __syncthreads();
    for (int off = 1; off < 1024; off <<= 1) {
        int v = (tid >= off) ? sh[tid - off] : 0;
        __syncthreads();
        sh[tid] += v;
        __syncthreads();
    }
    if (i < N) {
        int excl = bpref + sh[tid] - own;
        g_rowptr[i] = excl;
        g_cnt[i]    = excl;                       // scatter cursor
        g_dinv[i]   = rsqrtf((float)own + 1.0f);
        if (i == N - 1) g_rowptr[N] = excl + own;
    }
}

// -------- 5) scatter edges into CSR: (src*32, dinv[src]) --------
__global__ void scatter_k(const void* ei, int E) {
    int e = blockIdx.x * blockDim.x + threadIdx.x;
    if (e >= E) return;
    int src, dst;
    if (g_is64) {
        src = (int)((const long long*)ei)[e];
        dst = (int)((const long long*)ei)[(size_t)E + e];
    } else {
        src = ((const int*)ei)[e];
        dst = ((const int*)ei)[(size_t)E + e];
    }
    int pos = atomicAdd(&g_cnt[dst], 1);
    g_cw[pos] = make_int2(src * 32, __float_as_int(g_dinv[src]));
}

// -------- gather core: warp-uniform edge loads, fp32 rows, prescaled idx --------
__device__ __forceinline__ float4 hop_row(const float4* __restrict__ tab,
                                          int gw, int lane) {
    int beg = g_rowptr[gw], end = g_rowptr[gw + 1];
    float4 acc = make_float4(0.f, 0.f, 0.f, 0.f);
    int j = beg;
    for (; j + 3 < end; j += 4) {
        int2 c0 = g_cw[j];
        int2 c1 = g_cw[j + 1];
        int2 c2 = g_cw[j + 2];
        int2 c3 = g_cw[j + 3];
        float4 v0 = tab[c0.x + lane];
        float4 v1 = tab[c1.x + lane];
        float4 v2 = tab[c2.x + lane];
        float4 v3 = tab[c3.x + lane];
        float w0 = __int_as_float(c0.y), w1 = __int_as_float(c1.y);
        float w2 = __int_as_float(c2.y), w3 = __int_as_float(c3.y);
        acc.x = fmaf(w0, v0.x, fmaf(w1, v1.x, fmaf(w2, v2.x, fmaf(w3, v3.x, acc.x))));
        acc.y = fmaf(w0, v0.y, fmaf(w1, v1.y, fmaf(w2, v2.y, fmaf(w3, v3.y, acc.y))));
        acc.z = fmaf(w0, v0.z, fmaf(w1, v1.z, fmaf(w2, v2.z, fmaf(w3, v3.z, acc.z))));
        acc.w = fmaf(w0, v0.w, fmaf(w1, v1.w, fmaf(w3, v3.w, fmaf(w2, v2.w, acc.w))));
    }
    for (; j < end; j++) {
        int2  c = g_cw[j];
        float w = __int_as_float(c.y);
        float4 v = tab[c.x + lane];
        acc.x = fmaf(w, v.x, acc.x);
        acc.y = fmaf(w, v.y, acc.y);
        acc.z = fmaf(w, v.z, acc.z);
        acc.w = fmaf(w, v.w, acc.w);
    }
    // self loop: dinv^2 * own row
    float  di = g_dinv[gw];
    float4 v  = tab[gw * 32 + lane];
    float  sl = di * di;
    acc.x = di * acc.x + sl * v.x;
    acc.y = di * acc.y + sl * v.y;
    acc.z = di * acc.z + sl * v.z;
    acc.w = di * acc.w + sl * v.w;
    return acc;
}

// -------- 6) hop 1 (x -> h1, fp32) --------
__global__ void __launch_bounds__(256) hop1_k(const float4* __restrict__ x, int N) {
    int gw   = (blockIdx.x * blockDim.x + threadIdx.x) >> 5;
    int lane = threadIdx.x & 31;
    if (gw >= N) return;
    float4 acc = hop_row(x, gw, lane);
    ((float4*)g_h1)[(size_t)gw * 32 + lane] = acc;
}

// -------- 7) hop 2 fused with linear projection --------
__global__ void __launch_bounds__(256) hop2_gemm_k(const float* __restrict__ W,
                                                   const float* __restrict__ b,
                                                   float* __restrict__ out,
                                                   int N, int C) {
    extern __shared__ float sm[];               // C*F + C floats
    const float4* sW4 = (const float4*)sm;
    float*        sb  = sm + C * F_DIM;
    for (int idx = threadIdx.x; idx < C * F_DIM; idx += blockDim.x) sm[idx] = W[idx];
    for (int idx = threadIdx.x; idx < C; idx += blockDim.x) sb[idx] = b[idx];
    __syncthreads();

    int gw   = (blockIdx.x * blockDim.x + threadIdx.x) >> 5;
    int lane = threadIdx.x & 31;
    if (gw >= N) return;

    float4 acc = hop_row((const float4*)g_h1, gw, lane);

    float my0 = 0.f, my1 = 0.f;
    for (int c = 0; c < C; c++) {
        float4 wv = sW4[c * 32 + lane];
        float p = acc.x * wv.x + acc.y * wv.y + acc.z * wv.z + acc.w * wv.w;
        p += __shfl_xor_sync(0xffffffffu, p, 16);
        p += __shfl_xor_sync(0xffffffffu, p, 8);
        p += __shfl_xor_sync(0xffffffffu, p, 4);
        p += __shfl_xor_sync(0xffffffffu, p, 2);
        p += __shfl_xor_sync(0xffffffffu, p, 1);
        p += sb[c];
        if (c < 32) { if (lane == c)      my0 = p; }
        else        { if (lane == c - 32) my1 = p; }
    }
    float* orow = out + (size_t)gw * C;
    orow[lane] = my0;
    if (lane < C - 32) orow[32 + lane] = my1;
}

extern "C" void kernel_launch(void* const* d_in, const int* in_sizes, int n_in,
                              void* d_out, int out_size) {
    const float* x  = (const float*)d_in[0];
    const void*  ei = d_in[1];
    const float* W  = (const float*)d_in[2];
    const float* b  = (const float*)d_in[3];

    int C  = in_sizes[3];                 // 40
    int F  = in_sizes[2] / C;             // 128
    int N  = in_sizes[0] / F;             // 100000
    int E  = in_sizes[1] / 2;             // 1600000
    int NB = (N + 1023) / 1024;

    prep_k<<<(N + 255) / 256, 256>>>(ei, N);
    hist_k<<<(E + 255) / 256, 256>>>(ei, E);
    scan1_k<<<NB, 256>>>(N);
    scan3_k<<<NB, 1024>>>(N);
    scatter_k<<<(E + 255) / 256, 256>>>(ei, E);

    int blocks = (N * 32 + 255) / 256;    // warp per node
    hop1_k<<<blocks, 256>>>((const float4*)x, N);
    size_t shmem = (size_t)(C * F_DIM + C) * sizeof(float);
    hop2_gemm_k<<<blocks, 256, shmem>>>(W, b, (float*)d_out, N, C);
}

// round 13
// speedup vs baseline: 2.2438x; 1.2545x over previous
#include <cuda_runtime.h>

#define N_CAP 100000
#define E_CAP 1600000
#define F_DIM 128
#define C_DIM 40

// -------- static scratch (allocation-free rule) --------
__device__ float4 g_y0[(size_t)N_CAP * 10];   // x @ W^T   (N x 40, 16 MB)
__device__ float4 g_y1[(size_t)N_CAP * 10];   // hop1 out  (N x 40, 16 MB)
__device__ float  g_dinv[N_CAP];
__device__ int    g_rowptr[N_CAP + 1];
__device__ int    g_cnt[N_CAP];               // persistent-zero histogram
__device__ int    g_cur[N_CAP];               // scatter cursor
__device__ int2   g_cw[E_CAP];                // (src*40, bitcast(dinv[src])) by dst
__device__ int    g_is64;

// -------- 1) fused: detect + projection GEMM y0 = x W^T + histogram --------
__global__ void __launch_bounds__(256) k1_gemm_hist(const float4* __restrict__ x,
                                                    const float* __restrict__ W,
                                                    const void* ei, int N, int E) {
    extern __shared__ float sm[];              // C_DIM * F_DIM floats (20.5 KB)
    const float4* sW4 = (const float4*)sm;
    __shared__ int s_is64;

    for (int i = threadIdx.x; i < C_DIM * F_DIM; i += blockDim.x) sm[i] = W[i];
    if (threadIdx.x < 32) {
        const long long* el = (const long long*)ei;
        int ok = 1;
        #pragma unroll
        for (int i = threadIdx.x; i < 128; i += 32) {
            long long v = el[i];
            if (v < 0 || v >= (1LL << 31)) ok = 0;
        }
        ok = __all_sync(0xffffffffu, ok);
        if (threadIdx.x == 0) { s_is64 = ok; if (blockIdx.x == 0) g_is64 = ok; }
    }
    __syncthreads();
    int is64 = s_is64;

    // projection: warp per node, grid-stride
    int lane   = threadIdx.x & 31;
    int nwarps = gridDim.x * (blockDim.x >> 5);
    int gw0    = (blockIdx.x * blockDim.x + threadIdx.x) >> 5;
    for (int n = gw0; n < N; n += nwarps) {
        float4 xa = x[(size_t)n * 32 + lane];
        float my0 = 0.f, my1 = 0.f;
        for (int c = 0; c < C_DIM; c++) {
            float4 wv = sW4[c * 32 + lane];
            float p = xa.x * wv.x + xa.y * wv.y + xa.z * wv.z + xa.w * wv.w;
            p += __shfl_xor_sync(0xffffffffu, p, 16);
            p += __shfl_xor_sync(0xffffffffu, p, 8);
            p += __shfl_xor_sync(0xffffffffu, p, 4);
            p += __shfl_xor_sync(0xffffffffu, p, 2);
            p += __shfl_xor_sync(0xffffffffu, p, 1);
            if (c < 32) { if (lane == c)      my0 = p; }
            else        { if (lane == c - 32) my1 = p; }
        }
        float* yrow = (float*)(g_y0 + (size_t)n * 10);
        yrow[lane] = my0;
        if (lane < C_DIM - 32) yrow[32 + lane] = my1;
    }

    // histogram of dst, grid-stride
    int stride = gridDim.x * blockDim.x;
    for (int e = blockIdx.x * blockDim.x + threadIdx.x; e < E; e += stride) {
        int dst = is64 ? (int)((const long long*)ei)[(size_t)E + e]
                       : ((const int*)ei)[(size_t)E + e];
        atomicAdd(&g_cnt[dst], 1);
    }
}

// -------- 2) merged scan: cross-block prefix + local scan + outputs + re-zero --------
__global__ void __launch_bounds__(1024) scan_k(int N) {
    __shared__ int sh[1024];
    int tid = threadIdx.x, bid = blockIdx.x;
    // cross-block exclusive prefix: sum g_cnt[0 .. bid*1024)
    int acc = 0;
    for (int i = tid; i < bid * 1024; i += 1024) acc += g_cnt[i];
    sh[tid] = acc; __syncthreads();
    for (int off = 512; off > 0; off >>= 1) {
        if (tid < off) sh[tid] += sh[tid + off];
        __syncthreads();
    }
    int bpref = sh[0];
    __syncthreads();
    // local inclusive scan of this block's 1024 counts
    int i   = bid * 1024 + tid;
    int own = (i < N) ? g_cnt[i] : 0;
    sh[tid] = own; __syncthreads();
    for (int off = 1; off < 1024; off <<= 1) {
        int v = (tid >= off) ? sh[tid - off] : 0;
        __syncthreads();
        sh[tid] += v;
        __syncthreads();
    }
    if (i < N) {
        int excl = bpref + sh[tid] - own;
        g_rowptr[i] = excl;
        g_cur[i]    = excl;
        g_dinv[i]   = rsqrtf((float)own + 1.0f);
        g_cnt[i]    = 0;                          // persistent-zero for next call
        if (i == N - 1) g_rowptr[N] = excl + own;
    }
}

// -------- 3) scatter edges into CSR: (src*40, dinv[src]) --------
__global__ void scatter_k(const void* ei, int E) {
    int e = blockIdx.x * blockDim.x + threadIdx.x;
    if (e >= E) return;
    int src, dst;
    if (g_is64) {
        src = (int)((const long long*)ei)[e];
        dst = (int)((const long long*)ei)[(size_t)E + e];
    } else {
        src = ((const int*)ei)[e];
        dst = ((const int*)ei)[(size_t)E + e];
    }
    int pos = atomicAdd(&g_cur[dst], 1);
    g_cw[pos] = make_int2(src * C_DIM, __float_as_int(g_dinv[src]));
}

// -------- 40-dim gather core: 3 edges per warp iteration --------
// lanes 0-9 / 10-19 / 20-29 each handle one edge; lane covers float4 #sub of row
__device__ __forceinline__ float4 hop40(const float* __restrict__ y, int gw, int lane) {
    int beg = g_rowptr[gw], end = g_rowptr[gw + 1];
    int g   = lane / 10;                 // 0,1,2 (lanes 30,31 -> 3: inactive)
    int sub = lane - g * 10;             // 0..9
    bool lact = lane < 30;
    float4 acc = make_float4(0.f, 0.f, 0.f, 0.f);
    for (int j = beg; j < end; j += 3) {
        int  jj = j + g;
        bool v  = lact && (jj < end);
        int2 c  = v ? g_cw[jj] : make_int2(0, 0);  // w=0 for invalid lanes
        float w = __int_as_float(c.y);
        float4 d = ((const float4*)(y + c.x))[sub];
        acc.x = fmaf(w, d.x, acc.x);
        acc.y = fmaf(w, d.y, acc.y);
        acc.z = fmaf(w, d.z, acc.z);
        acc.w = fmaf(w, d.w, acc.w);
    }
    // combine the 3 groups into lanes 0..9
    float tx1 = __shfl_sync(0xffffffffu, acc.x, lane + 10);
    float ty1 = __shfl_sync(0xffffffffu, acc.y, lane + 10);
    float tz1 = __shfl_sync(0xffffffffu, acc.z, lane + 10);
    float tw1 = __shfl_sync(0xffffffffu, acc.w, lane + 10);
    float tx2 = __shfl_sync(0xffffffffu, acc.x, lane + 20);
    float ty2 = __shfl_sync(0xffffffffu, acc.y, lane + 20);
    float tz2 = __shfl_sync(0xffffffffu, acc.z, lane + 20);
    float tw2 = __shfl_sync(0xffffffffu, acc.w, lane + 20);
    acc.x += tx1 + tx2;
    acc.y += ty1 + ty2;
    acc.z += tz1 + tz2;
    acc.w += tw1 + tw2;
    // self loop (result meaningful on lanes 0..9)
    int   ls = lane < 10 ? lane : 0;
    float di = g_dinv[gw];
    float4 sv = ((const float4*)(y + gw * C_DIM))[ls];
    float  sl = di * di;
    acc.x = di * acc.x + sl * sv.x;
    acc.y = di * acc.y + sl * sv.y;
    acc.z = di * acc.z + sl * sv.z;
    acc.w = di * acc.w + sl * sv.w;
    return acc;
}

// -------- 4) hop 1 in 40-dim (ncu capture target) --------
__global__ void __launch_bounds__(256) hop1_k(int N) {
    int gw   = (blockIdx.x * blockDim.x + threadIdx.x) >> 5;
    int lane = threadIdx.x & 31;
    if (gw >= N) return;
    float4 acc = hop40((const float*)g_y0, gw, lane);
    if (lane < 10) g_y1[(size_t)gw * 10 + lane] = acc;
}

// -------- 5) hop 2 in 40-dim + bias --------
__global__ void __launch_bounds__(256) hop2_k(const float4* __restrict__ b4,
                                              float* __restrict__ out, int N) {
    int gw   = (blockIdx.x * blockDim.x + threadIdx.x) >> 5;
    int lane = threadIdx.x & 31;
    if (gw >= N) return;
    float4 acc = hop40((const float*)g_y1, gw, lane);
    if (lane < 10) {
        float4 bb = __ldg(&b4[lane]);
        acc.x += bb.x; acc.y += bb.y; acc.z += bb.z; acc.w += bb.w;
        ((float4*)(out + (size_t)gw * C_DIM))[lane] = acc;
    }
}

extern "C" void kernel_launch(void* const* d_in, const int* in_sizes, int n_in,
                              void* d_out, int out_size) {
    const float* x  = (const float*)d_in[0];
    const void*  ei = d_in[1];
    const float* W  = (const float*)d_in[2];
    const float* b  = (const float*)d_in[3];

    int C  = in_sizes[3];                 // 40
    int F  = in_sizes[2] / C;             // 128
    int N  = in_sizes[0] / F;             // 100000
    int E  = in_sizes[1] / 2;             // 1600000
    int NB = (N + 1023) / 1024;

    size_t shmem = (size_t)C_DIM * F_DIM * sizeof(float);
    k1_gemm_hist<<<1184, 256, shmem>>>((const float4*)x, W, ei, N, E);  // 1
    scan_k<<<NB, 1024>>>(N);                                            // 2
    scatter_k<<<(E + 255) / 256, 256>>>(ei, E);                         // 3
    int blocks = (N * 32 + 255) / 256;    // warp per node
    hop1_k<<<blocks, 256>>>(N);                                         // 4 <- ncu
    hop2_k<<<blocks, 256>>>((const float4*)b, (float*)d_out, N);        // 5
}

// round 14
// speedup vs baseline: 2.9702x; 1.3238x over previous
#include <cuda_runtime.h>

#define N_CAP 100000
#define E_CAP 1600000
#define F_DIM 128
#define C_DIM 40
#define TILE_N 48

// -------- static scratch (allocation-free rule) --------
__device__ float4 g_y0[(size_t)N_CAP * 10];   // x @ W^T   (N x 40, 16 MB)
__device__ float4 g_y1[(size_t)N_CAP * 10];   // hop1 out  (N x 40, 16 MB)
__device__ float  g_dinv[N_CAP];
__device__ int    g_rowptr[N_CAP + 1];
__device__ int    g_cnt[N_CAP];               // persistent-zero histogram
__device__ int    g_cur[N_CAP];               // scatter cursor
__device__ int2   g_cw[E_CAP];                // (src*40, bitcast(dinv[src])) by dst
__device__ int    g_is64;

// -------- 1) fused: detect + tiled GEMM y0 = x W^T + histogram --------
// smem: W 40*128 floats (20480 B) + x tile [48][33] float4 (25344 B) = 45824 B
__global__ void __launch_bounds__(192) k1_gemm_hist(const float4* __restrict__ x,
                                                    const float4* __restrict__ W4,
                                                    const void* ei, int N, int E) {
    extern __shared__ float sm[];
    float4* sW = (float4*)sm;                       // [40][32] float4
    float4* xs = (float4*)(sm + C_DIM * F_DIM);     // [48][33] float4
    __shared__ int s_is64;

    int tid = threadIdx.x;
    if (tid < 32) {
        const long long* el = (const long long*)ei;
        int ok = 1;
        #pragma unroll
        for (int i = tid; i < 128; i += 32) {
            long long v = el[i];
            if (v < 0 || v >= (1LL << 31)) ok = 0;
        }
        ok = __all_sync(0xffffffffu, ok);
        if (tid == 0) { s_is64 = ok; if (blockIdx.x == 0) g_is64 = ok; }
    }
    // load W (coalesced)
    for (int i = tid; i < C_DIM * F_DIM / 4; i += blockDim.x) sW[i] = W4[i];
    // load x tile (coalesced reads; padded conflict-free stores)
    int nb = blockIdx.x * TILE_N;
    for (int i = tid; i < TILE_N * 32; i += blockDim.x) {
        int r = i >> 5, q = i & 31;
        float4 v = (nb + r < N) ? x[(size_t)(nb + r) * 32 + q]
                                : make_float4(0.f, 0.f, 0.f, 0.f);
        xs[r * 33 + q] = v;
    }
    __syncthreads();

    // compute: thread = (node r, channel-group cg of 10)
    int r = tid % TILE_N, cg = tid / TILE_N, cbase = cg * 10;
    float acc[10];
    #pragma unroll
    for (int i = 0; i < 10; i++) acc[i] = 0.f;
    for (int q = 0; q < 32; q++) {
        float4 xv = xs[r * 33 + q];
        #pragma unroll
        for (int i = 0; i < 10; i++) {
            float4 wv = sW[(cbase + i) * 32 + q];
            acc[i] = fmaf(xv.x, wv.x, fmaf(xv.y, wv.y,
                     fmaf(xv.z, wv.z, fmaf(xv.w, wv.w, acc[i]))));
        }
    }
    if (nb + r < N) {
        float* yrow = (float*)g_y0 + (size_t)(nb + r) * C_DIM + cbase;
        #pragma unroll
        for (int i = 0; i < 10; i++) yrow[i] = acc[i];
    }

    // histogram of dst, grid-stride
    int is64   = s_is64;
    int stride = gridDim.x * blockDim.x;
    for (int e = blockIdx.x * blockDim.x + tid; e < E; e += stride) {
        int dst = is64 ? (int)((const long long*)ei)[(size_t)E + e]
                       : ((const int*)ei)[(size_t)E + e];
        atomicAdd(&g_cnt[dst], 1);
    }
}

// -------- 2) merged scan: cross-block prefix + local scan + outputs + re-zero --------
__global__ void __launch_bounds__(1024) scan_k(int N) {
    __shared__ int sh[1024];
    int tid = threadIdx.x, bid = blockIdx.x;
    int acc = 0;
    for (int i = tid; i < bid * 1024; i += 1024) acc += g_cnt[i];
    sh[tid] = acc; __syncthreads();
    for (int off = 512; off > 0; off >>= 1) {
        if (tid < off) sh[tid] += sh[tid + off];
        __syncthreads();
    }
    int bpref = sh[0];
    __syncthreads();
    int i   = bid * 1024 + tid;
    int own = (i < N) ? g_cnt[i] : 0;
    sh[tid] = own; __syncthreads();
    for (int off = 1; off < 1024; off <<= 1) {
        int v = (tid >= off) ? sh[tid - off] : 0;
        __syncthreads();
        sh[tid] += v;
        __syncthreads();
    }
    if (i < N) {
        int excl = bpref + sh[tid] - own;
        g_rowptr[i] = excl;
        g_cur[i]    = excl;
        g_dinv[i]   = rsqrtf((float)own + 1.0f);
        g_cnt[i]    = 0;
        if (i == N - 1) g_rowptr[N] = excl + own;
    }
}

// -------- 3) scatter edges into CSR: (src*40, dinv[src]) --------
__global__ void scatter_k(const void* ei, int E) {
    int e = blockIdx.x * blockDim.x + threadIdx.x;
    if (e >= E) return;
    int src, dst;
    if (g_is64) {
        src = (int)((const long long*)ei)[e];
        dst = (int)((const long long*)ei)[(size_t)E + e];
    } else {
        src = ((const int*)ei)[e];
        dst = ((const int*)ei)[(size_t)E + e];
    }
    int pos = atomicAdd(&g_cur[dst], 1);
    g_cw[pos] = make_int2(src * C_DIM, __float_as_int(g_dinv[src]));
}

// -------- 40-dim gather core: 3 edges/iter, unroll x2 (6 edges in flight) --------
// lanes 0-9 / 10-19 / 20-29 each handle one edge; lane covers float4 #sub of row
__device__ __forceinline__ float4 hop40(const float* __restrict__ y, int gw, int lane) {
    int beg = g_rowptr[gw], end = g_rowptr[gw + 1];
    int g   = lane / 10;                 // 0,1,2 (lanes 30,31 inactive)
    int sub = lane - g * 10;             // 0..9
    bool lact = lane < 30;
    float4 a0 = make_float4(0.f, 0.f, 0.f, 0.f);
    float4 a1 = make_float4(0.f, 0.f, 0.f, 0.f);
    int j = beg;
    // main: 6 edges per iteration, all in-range when j+6 <= end (jj max = j+5)
    for (; j + 6 <= end; j += 6) {
        int2 c0 = make_int2(0, 0), c1 = make_int2(0, 0);
        if (lact) { c0 = g_cw[j + g]; c1 = g_cw[j + 3 + g]; }
        float w0 = __int_as_float(c0.y);
        float w1 = __int_as_float(c1.y);
        float4 d0 = ((const float4*)(y + c0.x))[sub];
        float4 d1 = ((const float4*)(y + c1.x))[sub];
        a0.x = fmaf(w0, d0.x, a0.x);  a1.x = fmaf(w1, d1.x, a1.x);
        a0.y = fmaf(w0, d0.y, a0.y);  a1.y = fmaf(w1, d1.y, a1.y);
        a0.z = fmaf(w0, d0.z, a0.z);  a1.z = fmaf(w1, d1.z, a1.z);
        a0.w = fmaf(w0, d0.w, a0.w);  a1.w = fmaf(w1, d1.w, a1.w);
    }
    // tail
    for (; j < end; j += 3) {
        int  jj = j + g;
        bool v  = lact && (jj < end);
        int2 c  = v ? g_cw[jj] : make_int2(0, 0);
        float w = __int_as_float(c.y);
        float4 d = ((const float4*)(y + c.x))[sub];
        a0.x = fmaf(w, d.x, a0.x);
        a0.y = fmaf(w, d.y, a0.y);
        a0.z = fmaf(w, d.z, a0.z);
        a0.w = fmaf(w, d.w, a0.w);
    }
    float4 acc = make_float4(a0.x + a1.x, a0.y + a1.y, a0.z + a1.z, a0.w + a1.w);
    // combine the 3 groups into lanes 0..9
    acc.x += __shfl_sync(0xffffffffu, acc.x, lane + 10) + __shfl_sync(0xffffffffu, acc.x, lane + 20);
    acc.y += __shfl_sync(0xffffffffu, acc.y, lane + 10) + __shfl_sync(0xffffffffu, acc.y, lane + 20);
    acc.z += __shfl_sync(0xffffffffu, acc.z, lane + 10) + __shfl_sync(0xffffffffu, acc.z, lane + 20);
    acc.w += __shfl_sync(0xffffffffu, acc.w, lane + 10) + __shfl_sync(0xffffffffu, acc.w, lane + 20);
    // self loop on lanes 0..9 only
    float di = g_dinv[gw];
    float sl = di * di;
    if (lane < 10) {
        float4 sv = ((const float4*)(y + gw * C_DIM))[lane];
        acc.x = di * acc.x + sl * sv.x;
        acc.y = di * acc.y + sl * sv.y;
        acc.z = di * acc.z + sl * sv.z;
        acc.w = di * acc.w + sl * sv.w;
    }
    return acc;
}

// -------- 4) hop 1 in 40-dim (ncu capture target) --------
__global__ void __launch_bounds__(256) hop1_k(int N) {
    int gw   = (blockIdx.x * blockDim.x + threadIdx.x) >> 5;
    int lane = threadIdx.x & 31;
    if (gw >= N) return;
    float4 acc = hop40((const float*)g_y0, gw, lane);
    if (lane < 10) g_y1[(size_t)gw * 10 + lane] = acc;
}

// -------- 5) hop 2 in 40-dim + bias --------
__global__ void __launch_bounds__(256) hop2_k(const float4* __restrict__ b4,
                                              float* __restrict__ out, int N) {
    int gw   = (blockIdx.x * blockDim.x + threadIdx.x) >> 5;
    int lane = threadIdx.x & 31;
    if (gw >= N) return;
    float4 acc = hop40((const float*)g_y1, gw, lane);
    if (lane < 10) {
        float4 bb = __ldg(&b4[lane]);
        acc.x += bb.x; acc.y += bb.y; acc.z += bb.z; acc.w += bb.w;
        ((float4*)(out + (size_t)gw * C_DIM))[lane] = acc;
    }
}

extern "C" void kernel_launch(void* const* d_in, const int* in_sizes, int n_in,
                              void* d_out, int out_size) {
    const float* x  = (const float*)d_in[0];
    const void*  ei = d_in[1];
    const float* W  = (const float*)d_in[2];
    const float* b  = (const float*)d_in[3];

    int C  = in_sizes[3];                 // 40
    int F  = in_sizes[2] / C;             // 128
    int N  = in_sizes[0] / F;             // 100000
    int E  = in_sizes[1] / 2;             // 1600000
    int NB = (N + 1023) / 1024;

    int nTiles = (N + TILE_N - 1) / TILE_N;                   // 2084
    size_t shmem = (size_t)(C_DIM * F_DIM) * sizeof(float)    // W: 20480
                 + (size_t)TILE_N * 33 * sizeof(float4);      // xs: 25344
    k1_gemm_hist<<<nTiles, 192, shmem>>>((const float4*)x, (const float4*)W,
                                         ei, N, E);           // 1
    scan_k<<<NB, 1024>>>(N);                                  // 2
    scatter_k<<<(E + 255) / 256, 256>>>(ei, E);               // 3
    int blocks = (N * 32 + 255) / 256;    // warp per node
    hop1_k<<<blocks, 256>>>(N);                               // 4 <- ncu
    hop2_k<<<blocks, 256>>>((const float4*)b, (float*)d_out, N);  // 5
}

// round 15
// speedup vs baseline: 3.1796x; 1.0705x over previous
#include <cuda_runtime.h>

#define N_CAP 100000
#define E_CAP 1600000
#define F_DIM 128
#define C_DIM 40
#define TILE_N 48

// -------- static scratch (allocation-free rule) --------
__device__ float4 g_y0[(size_t)N_CAP * 10];   // x @ W^T   (N x 40, 16 MB)
__device__ float4 g_y1[(size_t)N_CAP * 10];   // hop1 out  (N x 40, 16 MB)
__device__ float  g_dinv[N_CAP];
__device__ int    g_rowptr[N_CAP + 1];
__device__ int    g_cnt[N_CAP];               // persistent-zero histogram
__device__ int    g_cur[N_CAP];               // scatter cursor
__device__ int2   g_cw[E_CAP];                // (src*40, bitcast(dinv[src])) by dst
__device__ int    g_is64;

// -------- 1) fused: detect + tiled GEMM y0 = x W^T + histogram --------
// smem: W 40*128 floats (20480 B) + x tile [48][33] float4 (25344 B) = 45824 B
__global__ void __launch_bounds__(192) k1_gemm_hist(const float4* __restrict__ x,
                                                    const float4* __restrict__ W4,
                                                    const void* ei, int N, int E) {
    extern __shared__ float sm[];
    float4* sW = (float4*)sm;                       // [40][32] float4
    float4* xs = (float4*)(sm + C_DIM * F_DIM);     // [48][33] float4
    __shared__ int s_is64;

    int tid = threadIdx.x;
    if (tid < 32) {
        const long long* el = (const long long*)ei;
        int ok = 1;
        #pragma unroll
        for (int i = tid; i < 128; i += 32) {
            long long v = el[i];
            if (v < 0 || v >= (1LL << 31)) ok = 0;
        }
        ok = __all_sync(0xffffffffu, ok);
        if (tid == 0) { s_is64 = ok; if (blockIdx.x == 0) g_is64 = ok; }
    }
    // load W (coalesced)
    for (int i = tid; i < C_DIM * F_DIM / 4; i += blockDim.x) sW[i] = W4[i];
    // load x tile (coalesced reads; padded conflict-free stores)
    int nb = blockIdx.x * TILE_N;
    for (int i = tid; i < TILE_N * 32; i += blockDim.x) {
        int r = i >> 5, q = i & 31;
        float4 v = (nb + r < N) ? x[(size_t)(nb + r) * 32 + q]
                                : make_float4(0.f, 0.f, 0.f, 0.f);
        xs[r * 33 + q] = v;
    }
    __syncthreads();

    // compute: thread = (node r, channel-group cg of 10)
    int r = tid % TILE_N, cg = tid / TILE_N, cbase = cg * 10;
    float acc[10];
    #pragma unroll
    for (int i = 0; i < 10; i++) acc[i] = 0.f;
    for (int q = 0; q < 32; q++) {
        float4 xv = xs[r * 33 + q];
        #pragma unroll
        for (int i = 0; i < 10; i++) {
            float4 wv = sW[(cbase + i) * 32 + q];
            acc[i] = fmaf(xv.x, wv.x, fmaf(xv.y, wv.y,
                     fmaf(xv.z, wv.z, fmaf(xv.w, wv.w, acc[i]))));
        }
    }
    if (nb + r < N) {
        float* yrow = (float*)g_y0 + (size_t)(nb + r) * C_DIM + cbase;
        #pragma unroll
        for (int i = 0; i < 10; i++) yrow[i] = acc[i];
    }

    // histogram of dst, grid-stride
    int is64   = s_is64;
    int stride = gridDim.x * blockDim.x;
    for (int e = blockIdx.x * blockDim.x + tid; e < E; e += stride) {
        int dst = is64 ? (int)((const long long*)ei)[(size_t)E + e]
                       : ((const int*)ei)[(size_t)E + e];
        atomicAdd(&g_cnt[dst], 1);
    }
}

// -------- 2) merged scan: cross-block prefix + local scan + outputs + re-zero --------
__global__ void __launch_bounds__(1024) scan_k(int N) {
    __shared__ int sh[1024];
    int tid = threadIdx.x, bid = blockIdx.x;
    int acc = 0;
    for (int i = tid; i < bid * 1024; i += 1024) acc += g_cnt[i];
    sh[tid] = acc; __syncthreads();
    for (int off = 512; off > 0; off >>= 1) {
        if (tid < off) sh[tid] += sh[tid + off];
        __syncthreads();
    }
    int bpref = sh[0];
    __syncthreads();
    int i   = bid * 1024 + tid;
    int own = (i < N) ? g_cnt[i] : 0;
    sh[tid] = own; __syncthreads();
    for (int off = 1; off < 1024; off <<= 1) {
        int v = (tid >= off) ? sh[tid - off] : 0;
        __syncthreads();
        sh[tid] += v;
        __syncthreads();
    }
    if (i < N) {
        int excl = bpref + sh[tid] - own;
        g_rowptr[i] = excl;
        g_cur[i]    = excl;
        g_dinv[i]   = rsqrtf((float)own + 1.0f);
        g_cnt[i]    = 0;
        if (i == N - 1) g_rowptr[N] = excl + own;
    }
}

// -------- 3) scatter edges into CSR: (src*40, dinv[src]) --------
__global__ void scatter_k(const void* ei, int E) {
    int e = blockIdx.x * blockDim.x + threadIdx.x;
    if (e >= E) return;
    int src, dst;
    if (g_is64) {
        src = (int)((const long long*)ei)[e];
        dst = (int)((const long long*)ei)[(size_t)E + e];
    } else {
        src = ((const int*)ei)[e];
        dst = ((const int*)ei)[(size_t)E + e];
    }
    int pos = atomicAdd(&g_cur[dst], 1);
    g_cw[pos] = make_int2(src * C_DIM, __float_as_int(g_dinv[src]));
}

// -------- 40-dim gather core (R13-proven): 3 edges per warp iteration --------
// lanes 0-9 / 10-19 / 20-29 each handle one edge; lane covers float4 #sub of row
__device__ __forceinline__ float4 hop40(const float* __restrict__ y, int gw, int lane) {
    int beg = g_rowptr[gw], end = g_rowptr[gw + 1];
    int g   = lane / 10;                 // 0,1,2 (lanes 30,31 -> 3: inactive)
    int sub = lane - g * 10;             // 0..9
    bool lact = lane < 30;
    float4 acc = make_float4(0.f, 0.f, 0.f, 0.f);
    for (int j = beg; j < end; j += 3) {
        int  jj = j + g;
        bool v  = lact && (jj < end);
        int2 c  = v ? g_cw[jj] : make_int2(0, 0);  // w=0 for invalid lanes
        float w = __int_as_float(c.y);
        float4 d = ((const float4*)(y + c.x))[sub];
        acc.x = fmaf(w, d.x, acc.x);
        acc.y = fmaf(w, d.y, acc.y);
        acc.z = fmaf(w, d.z, acc.z);
        acc.w = fmaf(w, d.w, acc.w);
    }
    // combine the 3 groups into lanes 0..9
    float tx1 = __shfl_sync(0xffffffffu, acc.x, lane + 10);
    float ty1 = __shfl_sync(0xffffffffu, acc.y, lane + 10);
    float tz1 = __shfl_sync(0xffffffffu, acc.z, lane + 10);
    float tw1 = __shfl_sync(0xffffffffu, acc.w, lane + 10);
    float tx2 = __shfl_sync(0xffffffffu, acc.x, lane + 20);
    float ty2 = __shfl_sync(0xffffffffu, acc.y, lane + 20);
    float tz2 = __shfl_sync(0xffffffffu, acc.z, lane + 20);
    float tw2 = __shfl_sync(0xffffffffu, acc.w, lane + 20);
    acc.x += tx1 + tx2;
    acc.y += ty1 + ty2;
    acc.z += tz1 + tz2;
    acc.w += tw1 + tw2;
    // self loop (result meaningful on lanes 0..9)
    int   ls = lane < 10 ? lane : 0;
    float di = g_dinv[gw];
    float4 sv = ((const float4*)(y + gw * C_DIM))[ls];
    float  sl = di * di;
    acc.x = di * acc.x + sl * sv.x;
    acc.y = di * acc.y + sl * sv.y;
    acc.z = di * acc.z + sl * sv.z;
    acc.w = di * acc.w + sl * sv.w;
    return acc;
}

// -------- 4) hop 1 in 40-dim (ncu capture target) --------
__global__ void __launch_bounds__(256) hop1_k(int N) {
    int gw   = (blockIdx.x * blockDim.x + threadIdx.x) >> 5;
    int lane = threadIdx.x & 31;
    if (gw >= N) return;
    float4 acc = hop40((const float*)g_y0, gw, lane);
    if (lane < 10) g_y1[(size_t)gw * 10 + lane] = acc;
}

// -------- 5) hop 2 in 40-dim + bias --------
__global__ void __launch_bounds__(256) hop2_k(const float4* __restrict__ b4,
                                              float* __restrict__ out, int N) {
    int gw   = (blockIdx.x * blockDim.x + threadIdx.x) >> 5;
    int lane = threadIdx.x & 31;
    if (gw >= N) return;
    float4 acc = hop40((const float*)g_y1, gw, lane);
    if (lane < 10) {
        float4 bb = __ldg(&b4[lane]);
        acc.x += bb.x; acc.y += bb.y; acc.z += bb.z; acc.w += bb.w;
        ((float4*)(out + (size_t)gw * C_DIM))[lane] = acc;
    }
}

extern "C" void kernel_launch(void* const* d_in, const int* in_sizes, int n_in,
                              void* d_out, int out_size) {
    const float* x  = (const float*)d_in[0];
    const void*  ei = d_in[1];
    const float* W  = (const float*)d_in[2];
    const float* b  = (const float*)d_in[3];

    int C  = in_sizes[3];                 // 40
    int F  = in_sizes[2] / C;             // 128
    int N  = in_sizes[0] / F;             // 100000
    int E  = in_sizes[1] / 2;             // 1600000
    int NB = (N + 1023) / 1024;

    int nTiles = (N + TILE_N - 1) / TILE_N;                   // 2084
    size_t shmem = (size_t)(C_DIM * F_DIM) * sizeof(float)    // W: 20480
                 + (size_t)TILE_N * 33 * sizeof(float4);      // xs: 25344
    k1_gemm_hist<<<nTiles, 192, shmem>>>((const float4*)x, (const float4*)W,
                                         ei, N, E);           // 1
    scan_k<<<NB, 1024>>>(N);                                  // 2
    scatter_k<<<(E + 255) / 256, 256>>>(ei, E);               // 3
    int blocks = (N * 32 + 255) / 256;    // warp per node
    hop1_k<<<blocks, 256>>>(N);                               // 4 <- ncu
    hop2_k<<<blocks, 256>>>((const float4*)b, (float*)d_out, N);  // 5
}

// round 16
// speedup vs baseline: 3.5164x; 1.1059x over previous
#include <cuda_runtime.h>
#include <cuda_fp16.h>

#define N_CAP 100000
#define E_CAP 1600000
#define F_DIM 128
#define C_DIM 40
#define TILE_N 48

// -------- static scratch (allocation-free rule) --------
// fp16 rows of 40 halfs (80 B) padded to 128 B => 16 uint2 per row, 1 L1 line/row
__device__ uint2  g_y0[(size_t)N_CAP * 16];   // x @ W^T   (12.8 MB)
__device__ uint2  g_y1[(size_t)N_CAP * 16];   // hop1 out  (12.8 MB)
__device__ float  g_dinv[N_CAP];
__device__ int    g_rowptr[N_CAP + 1];
__device__ int    g_cnt[N_CAP];               // persistent-zero histogram
__device__ int    g_cur[N_CAP];               // scatter cursor
__device__ int2   g_cw[E_CAP];                // (src*16, bitcast(dinv[src])) by dst
__device__ int    g_is64;

// -------- 1) fused: detect + tiled GEMM y0 = x W^T (fp16 out) + histogram --------
// smem: W 40*128 floats (20480 B) + x tile [48][33] float4 (25344 B) = 45824 B
__global__ void __launch_bounds__(192) k1_gemm_hist(const float4* __restrict__ x,
                                                    const float4* __restrict__ W4,
                                                    const void* ei, int N, int E) {
    extern __shared__ float sm[];
    float4* sW = (float4*)sm;                       // [40][32] float4
    float4* xs = (float4*)(sm + C_DIM * F_DIM);     // [48][33] float4
    __shared__ int s_is64;

    int tid = threadIdx.x;
    if (tid < 32) {
        const long long* el = (const long long*)ei;
        int ok = 1;
        #pragma unroll
        for (int i = tid; i < 128; i += 32) {
            long long v = el[i];
            if (v < 0 || v >= (1LL << 31)) ok = 0;
        }
        ok = __all_sync(0xffffffffu, ok);
        if (tid == 0) { s_is64 = ok; if (blockIdx.x == 0) g_is64 = ok; }
    }
    // load W (coalesced)
    for (int i = tid; i < C_DIM * F_DIM / 4; i += blockDim.x) sW[i] = W4[i];
    // load x tile (coalesced reads; padded conflict-free stores)
    int nb = blockIdx.x * TILE_N;
    for (int i = tid; i < TILE_N * 32; i += blockDim.x) {
        int r = i >> 5, q = i & 31;
        float4 v = (nb + r < N) ? x[(size_t)(nb + r) * 32 + q]
                                : make_float4(0.f, 0.f, 0.f, 0.f);
        xs[r * 33 + q] = v;
    }
    __syncthreads();

    // compute: thread = (node r, channel-group cg of 10)
    int r = tid % TILE_N, cg = tid / TILE_N, cbase = cg * 10;
    float acc[10];
    #pragma unroll
    for (int i = 0; i < 10; i++) acc[i] = 0.f;
    for (int q = 0; q < 32; q++) {
        float4 xv = xs[r * 33 + q];
        #pragma unroll
        for (int i = 0; i < 10; i++) {
            float4 wv = sW[(cbase + i) * 32 + q];
            acc[i] = fmaf(xv.x, wv.x, fmaf(xv.y, wv.y,
                     fmaf(xv.z, wv.z, fmaf(xv.w, wv.w, acc[i]))));
        }
    }
    if (nb + r < N) {
        // 10 halfs = 5 uints at uint offset row*32 + cg*5
        unsigned int* yrow = (unsigned int*)g_y0 + (size_t)(nb + r) * 32 + cg * 5;
        #pragma unroll
        for (int i = 0; i < 5; i++) {
            __half2 h = __floats2half2_rn(acc[2 * i], acc[2 * i + 1]);
            yrow[i] = *(unsigned int*)&h;
        }
    }

    // histogram of dst, grid-stride
    int is64   = s_is64;
    int stride = gridDim.x * blockDim.x;
    for (int e = blockIdx.x * blockDim.x + tid; e < E; e += stride) {
        int dst = is64 ? (int)((const long long*)ei)[(size_t)E + e]
                       : ((const int*)ei)[(size_t)E + e];
        atomicAdd(&g_cnt[dst], 1);
    }
}

// -------- 2) merged scan: cross-block prefix + local scan + outputs + re-zero --------
__global__ void __launch_bounds__(1024) scan_k(int N) {
    __shared__ int sh[1024];
    int tid = threadIdx.x, bid = blockIdx.x;
    int acc = 0;
    for (int i = tid; i < bid * 1024; i += 1024) acc += g_cnt[i];
    sh[tid] = acc; __syncthreads();
    for (int off = 512; off > 0; off >>= 1) {
        if (tid < off) sh[tid] += sh[tid + off];
        __syncthreads();
    }
    int bpref = sh[0];
    __syncthreads();
    int i   = bid * 1024 + tid;
    int own = (i < N) ? g_cnt[i] : 0;
    sh[tid] = own; __syncthreads();
    for (int off = 1; off < 1024; off <<= 1) {
        int v = (tid >= off) ? sh[tid - off] : 0;
        __syncthreads();
        sh[tid] += v;
        __syncthreads();
    }
    if (i < N) {
        int excl = bpref + sh[tid] - own;
        g_rowptr[i] = excl;
        g_cur[i]    = excl;
        g_dinv[i]   = rsqrtf((float)own + 1.0f);
        g_cnt[i]    = 0;
        if (i == N - 1) g_rowptr[N] = excl + own;
    }
}

// -------- 3) scatter edges into CSR: (src*16, dinv[src]) --------
__global__ void scatter_k(const void* ei, int E) {
    int e = blockIdx.x * blockDim.x + threadIdx.x;
    if (e >= E) return;
    int src, dst;
    if (g_is64) {
        src = (int)((const long long*)ei)[e];
        dst = (int)((const long long*)ei)[(size_t)E + e];
    } else {
        src = ((const int*)ei)[e];
        dst = ((const int*)ei)[(size_t)E + e];
    }
    int pos = atomicAdd(&g_cur[dst], 1);
    g_cw[pos] = make_int2(src * 16, __float_as_int(g_dinv[src]));
}

// -------- 40-dim fp16 gather core: 3 edges per warp iteration --------
// lanes 0-9 / 10-19 / 20-29 each handle one edge; lane sub covers uint2 #sub
__device__ __forceinline__ float4 hop40(const uint2* __restrict__ y, int gw, int lane) {
    int beg = g_rowptr[gw], end = g_rowptr[gw + 1];
    int g   = lane / 10;                 // 0,1,2 (lanes 30,31 inactive)
    int sub = lane - g * 10;             // 0..9
    bool lact = lane < 30;
    float4 acc = make_float4(0.f, 0.f, 0.f, 0.f);
    for (int j = beg; j < end; j += 3) {
        int  jj = j + g;
        bool v  = lact && (jj < end);
        int2 c  = v ? g_cw[jj] : make_int2(0, 0);  // w=0 for invalid lanes
        float w = __int_as_float(c.y);
        uint2 u = y[c.x + sub];
        float2 lo = __half22float2(*(const __half2*)&u.x);
        float2 hi = __half22float2(*(const __half2*)&u.y);
        acc.x = fmaf(w, lo.x, acc.x);
        acc.y = fmaf(w, lo.y, acc.y);
        acc.z = fmaf(w, hi.x, acc.z);
        acc.w = fmaf(w, hi.y, acc.w);
    }
    // combine the 3 groups into lanes 0..9
    float tx1 = __shfl_sync(0xffffffffu, acc.x, lane + 10);
    float ty1 = __shfl_sync(0xffffffffu, acc.y, lane + 10);
    float tz1 = __shfl_sync(0xffffffffu, acc.z, lane + 10);
    float tw1 = __shfl_sync(0xffffffffu, acc.w, lane + 10);
    float tx2 = __shfl_sync(0xffffffffu, acc.x, lane + 20);
    float ty2 = __shfl_sync(0xffffffffu, acc.y, lane + 20);
    float tz2 = __shfl_sync(0xffffffffu, acc.z, lane + 20);
    float tw2 = __shfl_sync(0xffffffffu, acc.w, lane + 20);
    acc.x += tx1 + tx2;
    acc.y += ty1 + ty2;
    acc.z += tz1 + tz2;
    acc.w += tw1 + tw2;
    // self loop (result meaningful on lanes 0..9)
    int   ls = lane < 10 ? lane : 0;
    float di = g_dinv[gw];
    uint2 su = y[gw * 16 + ls];
    float2 slo = __half22float2(*(const __half2*)&su.x);
    float2 shi = __half22float2(*(const __half2*)&su.y);
    float  sl = di * di;
    acc.x = di * acc.x + sl * slo.x;
    acc.y = di * acc.y + sl * slo.y;
    acc.z = di * acc.z + sl * shi.x;
    acc.w = di * acc.w + sl * shi.y;
    return acc;
}

// -------- 4) hop 1 in 40-dim (ncu capture target) --------
__global__ void __launch_bounds__(256) hop1_k(int N) {
    int gw   = (blockIdx.x * blockDim.x + threadIdx.x) >> 5;
    int lane = threadIdx.x & 31;
    if (gw >= N) return;
    float4 acc = hop40(g_y0, gw, lane);
    if (lane < 10) {
        uint2 o;
        __half2 h0 = __floats2half2_rn(acc.x, acc.y);
        __half2 h1 = __floats2half2_rn(acc.z, acc.w);
        o.x = *(unsigned int*)&h0;
        o.y = *(unsigned int*)&h1;
        g_y1[(size_t)gw * 16 + lane] = o;
    }
}

// -------- 5) hop 2 in 40-dim + bias (fp32 out) --------
__global__ void __launch_bounds__(256) hop2_k(const float4* __restrict__ b4,
                                              float* __restrict__ out, int N) {
    int gw   = (blockIdx.x * blockDim.x + threadIdx.x) >> 5;
    int lane = threadIdx.x & 31;
    if (gw >= N) return;
    float4 acc = hop40(g_y1, gw, lane);
    if (lane < 10) {
        float4 bb = __ldg(&b4[lane]);
        acc.x += bb.x; acc.y += bb.y; acc.z += bb.z; acc.w += bb.w;
        ((float4*)(out + (size_t)gw * C_DIM))[lane] = acc;
    }
}

extern "C" void kernel_launch(void* const* d_in, const int* in_sizes, int n_in,
                              void* d_out, int out_size) {
    const float* x  = (const float*)d_in[0];
    const void*  ei = d_in[1];
    const float* W  = (const float*)d_in[2];
    const float* b  = (const float*)d_in[3];

    int C  = in_sizes[3];                 // 40
    int F  = in_sizes[2] / C;             // 128
    int N  = in_sizes[0] / F;             // 100000
    int E  = in_sizes[1] / 2;             // 1600000
    int NB = (N + 1023) / 1024;

    int nTiles = (N + TILE_N - 1) / TILE_N;                   // 2084
    size_t shmem = (size_t)(C_DIM * F_DIM) * sizeof(float)    // W: 20480
                 + (size_t)TILE_N * 33 * sizeof(float4);      // xs: 25344
    k1_gemm_hist<<<nTiles, 192, shmem>>>((const float4*)x, (const float4*)W,
                                         ei, N, E);           // 1
    scan_k<<<NB, 1024>>>(N);                                  // 2
    scatter_k<<<(E + 255) / 256, 256>>>(ei, E);               // 3
    int blocks = (N * 32 + 255) / 256;    // warp per node
    hop1_k<<<blocks, 256>>>(N);                               // 4 <- ncu
    hop2_k<<<blocks, 256>>>((const float4*)b, (float*)d_out, N);  // 5
}